// round 10
// baseline (speedup 1.0000x reference)
#include <cuda_runtime.h>

// BlinnPhongShaderEnvMap: H=512, W=512 pixels, K=128 lights.
// Two lights per iteration via sm_103a packed f32x2 FMA (FFMA2).
// Output: concat(colors (H,W,3), n (H,W,3)) = 1572864 f32

#define NPIX (512 * 512)
#define K 128
#define KP (K / 2)   // light pairs

typedef unsigned long long u64;

__device__ __forceinline__ u64 pk2(float lo, float hi) {
    u64 r;
    asm("mov.b64 %0, {%1, %2};" : "=l"(r) : "f"(lo), "f"(hi));
    return r;
}
__device__ __forceinline__ void unpk2(u64 v, float& lo, float& hi) {
    asm("mov.b64 {%0, %1}, %2;" : "=f"(lo), "=f"(hi) : "l"(v));
}
__device__ __forceinline__ u64 fma2(u64 a, u64 b, u64 c) {
    u64 d;
    asm("fma.rn.f32x2 %0, %1, %2, %3;" : "=l"(d) : "l"(a), "l"(b), "l"(c));
    return d;
}
__device__ __forceinline__ u64 mul2(u64 a, u64 b) {
    u64 d;
    asm("mul.rn.f32x2 %0, %1, %2;" : "=l"(d) : "l"(a), "l"(b));
    return d;
}
__device__ __forceinline__ u64 add2(u64 a, u64 b) {
    u64 d;
    asm("add.rn.f32x2 %0, %1, %2;" : "=l"(d) : "l"(a), "l"(b));
    return d;
}

__global__ __launch_bounds__(256)
void blinn_phong_kernel(const float* __restrict__ pn,
                        const float* __restrict__ pd,
                        const float* __restrict__ cam,
                        const float* __restrict__ ld,
                        const float* __restrict__ lc,
                        const float* __restrict__ shin_p,
                        const float* __restrict__ kd_p,
                        const float* __restrict__ ks_p,
                        float* __restrict__ out) {
    // SoA packed-pair light data: element i holds lights (2i, 2i+1).
    __shared__ u64 sLx[KP], sLy[KP], sLz[KP];
    __shared__ u64 sCr[KP], sCg[KP], sCb[KP];

    const int tid = threadIdx.x;
    for (int i = tid; i < KP; i += blockDim.x) {
        sLx[i] = pk2(ld[6 * i + 0], ld[6 * i + 3]);
        sLy[i] = pk2(ld[6 * i + 1], ld[6 * i + 4]);
        sLz[i] = pk2(ld[6 * i + 2], ld[6 * i + 5]);
        sCr[i] = pk2(lc[6 * i + 0], lc[6 * i + 3]);
        sCg[i] = pk2(lc[6 * i + 1], lc[6 * i + 4]);
        sCb[i] = pk2(lc[6 * i + 2], lc[6 * i + 5]);
    }
    __syncthreads();

    const int p = blockIdx.x * blockDim.x + tid;
    if (p >= NPIX) return;

    // --- normalize pixel normal (matches F.normalize eps=1e-6) ---
    float nx = pn[3 * p + 0];
    float ny = pn[3 * p + 1];
    float nz = pn[3 * p + 2];
    {
        float nn = nx * nx + ny * ny + nz * nz;
        float inv = rsqrtf(fmaxf(nn, 1e-12f));  // == 1/max(sqrt(nn),1e-6)
        nx *= inv; ny *= inv; nz *= inv;
    }

    // --- view direction v = normalize(cam - pixel_direction) ---
    float vx = cam[0] - pd[3 * p + 0];
    float vy = cam[1] - pd[3 * p + 1];
    float vz = cam[2] - pd[3 * p + 2];
    {
        float vv = vx * vx + vy * vy + vz * vz;
        float inv = rsqrtf(fmaxf(vv, 1e-12f));
        vx *= inv; vy *= inv; vz *= inv;
    }

    const float nv   = nx * vx + ny * vy + nz * vz;
    const float shin = shin_p[0];
    const float kdv  = kd_p[0];
    const float ksv  = ks_p[0];

    // broadcast packs (one-time)
    const u64 nx2 = pk2(nx, nx), ny2 = pk2(ny, ny), nz2 = pk2(nz, nz);
    const u64 vx2 = pk2(vx, vx), vy2 = pk2(vy, vy), vz2 = pk2(vz, vz);
    const u64 nv2 = pk2(nv, nv);
    const u64 two2 = pk2(2.0f, 2.0f);

    // packed accumulators (even light in lo, odd light in hi)
    u64 dr2 = 0, dg2 = 0, db2 = 0;   // diffuse
    u64 sr2 = 0, sg2 = 0, sb2 = 0;   // specular

#pragma unroll 8
    for (int i = 0; i < KP; i++) {
        const u64 lx2 = sLx[i];
        const u64 ly2 = sLy[i];
        const u64 lz2 = sLz[i];

        // packed dot products for both lights
        const u64 nl2 = fma2(nx2, lx2, fma2(ny2, ly2, mul2(nz2, lz2)));
        const u64 vl2 = fma2(vx2, lx2, fma2(vy2, ly2, mul2(vz2, lz2)));

        // |v+L|^2 = 2 + 2*v.L (both unit vectors), packed
        const u64 h22 = fma2(two2, vl2, two2);
        // nv + nl packed
        const u64 q2 = add2(nv2, nl2);

        float nl0, nl1, h0, h1, q0, q1;
        unpk2(nl2, nl0, nl1);
        unpk2(h22, h0, h1);
        unpk2(q2, q0, q1);

        // diffuse clamp (single-op .SAT each)
        const float d0 = __saturatef(nl0);
        const float d1 = __saturatef(nl1);

        // specular: dot(n, normalize(v+L)) = (nv+nl)*rsqrt(|v+L|^2)
        // F.normalize eps: divide by max(|v+L|,1e-6) == *rsqrt(max(|v+L|^2,1e-12))
        const float r0 = rsqrtf(fmaxf(h0, 1e-12f));
        const float r1 = rsqrtf(fmaxf(h1, 1e-12f));
        float s0 = __saturatef(q0 * r0);
        float s1 = __saturatef(q1 * r1);
        s0 = exp2f(shin * __log2f(s0));   // log2(0)=-inf -> exp2 -> 0, correct
        s1 = exp2f(shin * __log2f(s1));

        const u64 d2 = pk2(d0, d1);
        const u64 s2 = pk2(s0, s1);

        const u64 cr2 = sCr[i];
        const u64 cg2 = sCg[i];
        const u64 cb2 = sCb[i];

        dr2 = fma2(cr2, d2, dr2);
        dg2 = fma2(cg2, d2, dg2);
        db2 = fma2(cb2, d2, db2);
        sr2 = fma2(cr2, s2, sr2);
        sg2 = fma2(cg2, s2, sg2);
        sb2 = fma2(cb2, s2, sb2);
    }

    // horizontal reduction of packed accumulators
    float a, b;
    unpk2(dr2, a, b); const float dr = a + b;
    unpk2(dg2, a, b); const float dg = a + b;
    unpk2(db2, a, b); const float db = a + b;
    unpk2(sr2, a, b); const float sr = a + b;
    unpk2(sg2, a, b); const float sg = a + b;
    unpk2(sb2, a, b); const float sb = a + b;

    // norm_factor = (shin+2) / (4*(2 - exp(-shin/2)))
    const float nf  = (shin + 2.f) / (4.f * (2.f - __expf(-0.5f * shin)));
    const float kss = nf * ksv;

    // output 0: colors
    out[3 * p + 0] = kdv * dr + kss * sr;
    out[3 * p + 1] = kdv * dg + kss * sg;
    out[3 * p + 2] = kdv * db + kss * sb;

    // output 1: normalized normals
    out[3 * NPIX + 3 * p + 0] = nx;
    out[3 * NPIX + 3 * p + 1] = ny;
    out[3 * NPIX + 3 * p + 2] = nz;
}

extern "C" void kernel_launch(void* const* d_in, const int* in_sizes, int n_in,
                              void* d_out, int out_size) {
    const float* pn   = (const float*)d_in[0];
    const float* pd   = (const float*)d_in[1];
    const float* cam  = (const float*)d_in[2];
    const float* ld   = (const float*)d_in[3];
    const float* lc   = (const float*)d_in[4];
    const float* shin = (const float*)d_in[5];
    const float* kd   = (const float*)d_in[6];
    const float* ks   = (const float*)d_in[7];
    float* out = (float*)d_out;

    const int threads = 256;
    const int blocks = (NPIX + threads - 1) / threads;
    blinn_phong_kernel<<<blocks, threads>>>(pn, pd, cam, ld, lc, shin, kd, ks, out);
}